// round 1
// baseline (speedup 1.0000x reference)
#include <cuda_runtime.h>

// Performer (FAVOR+) attention, fp32 SIMT implementation.
// B=64, N=2048, d=64, m=266 (padded to 288).

#define B_      64
#define N_      2048
#define D_      64
#define M_      266
#define MP_     288
#define NROWS_  (B_ * N_)              // 131072 rows per tensor
#define SCALE_  0.35355339059327373f   // 64^-0.25
#define NORMC_  0.0625f                // 0.5 * 64^-0.5
#define RATIO_  0.06131393394849658f   // 266^-0.5
#define EPS_    1e-4f

// ---------------- scratch (static device memory; no allocations) ----------------
__device__ float g_qdash[NROWS_ * MP_];   // ~151 MB
__device__ float g_kdash[NROWS_ * MP_];   // ~151 MB
__device__ float g_qnorm[NROWS_];
__device__ float g_knorm[NROWS_];
__device__ float g_qmax[NROWS_];
__device__ float g_kpart[16384];
__device__ float g_kmaxf;
__device__ float g_ctx[B_ * MP_ * D_];    // context + padding rows (padding stays 0)
__device__ float g_ksum[B_ * MP_];
__device__ float g_dinv[NROWS_];

// ---------------- K0: zero the context accumulator (graph replays!) -------------
__global__ void k0_zero() {
    int i = blockIdx.x * 256 + threadIdx.x;
    if (i < B_ * MP_ * D_) g_ctx[i] = 0.f;
}

// ---------------- K1: dash = SCALE * X @ P^T  (+ row norms) ---------------------
// Grid: (1024 row-tiles of 128, 2 col-tiles of 144). 288 threads (16 ty x 18 tx),
// micro tile 8 rows x 8 cols (cols split {tx*4, 72+tx*4}). K=64 in two stages.
__global__ __launch_bounds__(288, 2)
void k1_proj(const float* __restrict__ X, const float* __restrict__ P, int isq) {
    __shared__ float a_s[32][132];
    __shared__ float b_s[32][148];
    float* dash  = isq ? g_qdash : g_kdash;
    float* norms = isq ? g_qnorm : g_knorm;

    const int tid  = threadIdx.x;
    const int row0 = blockIdx.x * 128;
    const int m0   = blockIdx.y * 144;
    const int ty   = tid / 18;
    const int tx   = tid % 18;

    float acc[8][8];
#pragma unroll
    for (int i = 0; i < 8; i++)
#pragma unroll
        for (int j = 0; j < 8; j++) acc[i][j] = 0.f;
    float nacc = 0.f;

    const float4* X4 = (const float4*)X;
    const float4* P4 = (const float4*)P;

    for (int kb = 0; kb < 64; kb += 32) {
        const int kb4 = kb >> 2;
        // stage X tile (128 rows x 32 k), transposed into a_s[k][row]
        for (int i = tid; i < 1024; i += 288) {
            int r = i >> 3, k4 = i & 7;
            float4 v = X4[(row0 + r) * 16 + kb4 + k4];
            a_s[k4 * 4 + 0][r] = v.x; a_s[k4 * 4 + 1][r] = v.y;
            a_s[k4 * 4 + 2][r] = v.z; a_s[k4 * 4 + 3][r] = v.w;
        }
        // stage P tile (144 m x 32 k), scaled, transposed into b_s[k][m]
        for (int i = tid; i < 1152; i += 288) {
            int m = i >> 3, k4 = i & 7;
            float4 v = make_float4(0.f, 0.f, 0.f, 0.f);
            if (m0 + m < M_) v = P4[(m0 + m) * 16 + kb4 + k4];
            b_s[k4 * 4 + 0][m] = v.x * SCALE_; b_s[k4 * 4 + 1][m] = v.y * SCALE_;
            b_s[k4 * 4 + 2][m] = v.z * SCALE_; b_s[k4 * 4 + 3][m] = v.w * SCALE_;
        }
        __syncthreads();

        if (blockIdx.y == 0 && tid < 128) {
#pragma unroll 8
            for (int k = 0; k < 32; k++) { float v = a_s[k][tid]; nacc += v * v; }
        }

#pragma unroll 4
        for (int k = 0; k < 32; k++) {
            float4 a0 = *(const float4*)&a_s[k][ty * 8];
            float4 a1 = *(const float4*)&a_s[k][ty * 8 + 4];
            float4 b0 = *(const float4*)&b_s[k][tx * 4];
            float4 b1 = *(const float4*)&b_s[k][72 + tx * 4];
            float av[8] = {a0.x, a0.y, a0.z, a0.w, a1.x, a1.y, a1.z, a1.w};
            float bv[8] = {b0.x, b0.y, b0.z, b0.w, b1.x, b1.y, b1.z, b1.w};
#pragma unroll
            for (int i = 0; i < 8; i++)
#pragma unroll
                for (int j = 0; j < 8; j++) acc[i][j] += av[i] * bv[j];
        }
        __syncthreads();
    }

    if (blockIdx.y == 0 && tid < 128) norms[row0 + tid] = NORMC_ * nacc;

#pragma unroll
    for (int i = 0; i < 8; i++) {
        int gr = row0 + ty * 8 + i;
        float* dst = dash + gr * MP_ + m0;
        *(float4*)(dst + tx * 4) =
            make_float4(acc[i][0], acc[i][1], acc[i][2], acc[i][3]);
        *(float4*)(dst + 72 + tx * 4) =
            make_float4(acc[i][4], acc[i][5], acc[i][6], acc[i][7]);
    }
}

// ---------------- K1b: per-row max (q) + per-block max partials (k) -------------
// 32768 blocks x 256 thr; warp per row. Blocks [0,16384): q rows. Rest: k rows.
__global__ void k1b_max() {
    const int warp = threadIdx.x >> 5;
    const int lane = threadIdx.x & 31;
    const bool isq = blockIdx.x < 16384;
    const int row = (isq ? blockIdx.x : blockIdx.x - 16384) * 8 + warp;
    const float* rp = (isq ? g_qdash : g_kdash) + (size_t)row * MP_;
    float mx = -3.4e38f;
#pragma unroll
    for (int i = 0; i < 9; i++) {
        int m = lane + 32 * i;
        if (m < M_) mx = fmaxf(mx, rp[m]);
    }
#pragma unroll
    for (int o = 16; o; o >>= 1) mx = fmaxf(mx, __shfl_xor_sync(0xffffffffu, mx, o));
    if (isq) {
        if (lane == 0) g_qmax[row] = mx;
    } else {
        __shared__ float sm[8];
        if (lane == 0) sm[warp] = mx;
        __syncthreads();
        if (threadIdx.x == 0) {
            float m2 = sm[0];
#pragma unroll
            for (int i = 1; i < 8; i++) m2 = fmaxf(m2, sm[i]);
            g_kpart[blockIdx.x - 16384] = m2;
        }
    }
}

// ---------------- K1c: reduce block partials to the global k max -----------------
__global__ void k1c_kmax() {
    __shared__ float sm[256];
    float mx = -3.4e38f;
    for (int i = threadIdx.x; i < 16384; i += 256) mx = fmaxf(mx, g_kpart[i]);
    sm[threadIdx.x] = mx;
    __syncthreads();
    for (int s = 128; s; s >>= 1) {
        if (threadIdx.x < s) sm[threadIdx.x] = fmaxf(sm[threadIdx.x], sm[threadIdx.x + s]);
        __syncthreads();
    }
    if (threadIdx.x == 0) g_kmaxf = sm[0];
}

// ---------------- K2: context[b] += kp^T @ v (exp fused into staging) ------------
// Grid (3 m-tiles of 96, 4 n-slices of 512, 64 b). 192 thr (12 ty x 16 tx), 8x4 micro.
__global__ __launch_bounds__(192, 4)
void k2_ctx(const float* __restrict__ v) {
    __shared__ float kp_s[16][100];
    __shared__ float v_s[16][68];
    const int tid   = threadIdx.x;
    const int b     = blockIdx.z;
    const int m0    = blockIdx.x * 96;
    const int nbase = blockIdx.y * 512;
    const int ty = tid >> 4, tx = tid & 15;
    const int nn_l = tid & 15;   // staging: which n row
    const int mh   = tid >> 4;   // staging: which 8-wide m chunk (0..11)
    const float kmax = g_kmaxf;

    float acc[8][4];
#pragma unroll
    for (int i = 0; i < 8; i++)
#pragma unroll
        for (int j = 0; j < 4; j++) acc[i][j] = 0.f;

    for (int ck = 0; ck < 32; ck++) {
        const int n0 = nbase + ck * 16;
        {
            const int gr = b * N_ + n0 + nn_l;
            const float nrm = g_knorm[gr];
            const float* src = g_kdash + gr * MP_ + m0 + mh * 8;
            float4 d0 = *(const float4*)src;
            float4 d1 = *(const float4*)(src + 4);
            float dv[8] = {d0.x, d0.y, d0.z, d0.w, d1.x, d1.y, d1.z, d1.w};
            float kp[8];
#pragma unroll
            for (int j = 0; j < 8; j++) {
                int mg = m0 + mh * 8 + j;
                kp[j] = (mg < M_) ? RATIO_ * (__expf(dv[j] - nrm - kmax) + EPS_) : 0.f;
            }
            *(float4*)&kp_s[nn_l][mh * 8]     = make_float4(kp[0], kp[1], kp[2], kp[3]);
            *(float4*)&kp_s[nn_l][mh * 8 + 4] = make_float4(kp[4], kp[5], kp[6], kp[7]);
        }
        for (int i = tid; i < 1024; i += 192) {
            int nn = i >> 6, e = i & 63;
            v_s[nn][e] = v[(b * N_ + n0 + nn) * 64 + e];
        }
        __syncthreads();
#pragma unroll
        for (int nn = 0; nn < 16; nn++) {
            float4 a0 = *(const float4*)&kp_s[nn][ty * 8];
            float4 a1 = *(const float4*)&kp_s[nn][ty * 8 + 4];
            float4 b4 = *(const float4*)&v_s[nn][tx * 4];
            float av[8] = {a0.x, a0.y, a0.z, a0.w, a1.x, a1.y, a1.z, a1.w};
            float bv[4] = {b4.x, b4.y, b4.z, b4.w};
#pragma unroll
            for (int i = 0; i < 8; i++)
#pragma unroll
                for (int j = 0; j < 4; j++) acc[i][j] += av[i] * bv[j];
        }
        __syncthreads();
    }
#pragma unroll
    for (int i = 0; i < 8; i++)
#pragma unroll
        for (int j = 0; j < 4; j++)
            atomicAdd(&g_ctx[(b * MP_ + m0 + ty * 8 + i) * 64 + tx * 4 + j], acc[i][j]);
}

// ---------------- K2b: ksum[b,m] = sum_n kp[b,n,m] -------------------------------
__global__ void k2b_ksum() {
    const int g = blockIdx.x * 256 + threadIdx.x;   // exactly B_*MP_ threads
    const int b = g / MP_, m = g % MP_;
    float s = 0.f;
    if (m < M_) {
        const float kmax = g_kmaxf;
        const float* dp = g_kdash + (size_t)b * N_ * MP_ + m;
        const float* np = g_knorm + b * N_;
        float e = 0.f;
#pragma unroll 8
        for (int n = 0; n < N_; n++) e += __expf(dp[n * MP_] - np[n] - kmax);
        s = RATIO_ * (e + (float)N_ * EPS_);
    }
    g_ksum[g] = s;
}

// ---------------- K3b: dinv[row] = 1 / (qp_row . ksum[b]) ------------------------
__global__ void k3b_dinv() {
    const int warp = threadIdx.x >> 5, lane = threadIdx.x & 31;
    const int row = blockIdx.x * 8 + warp;
    const int b = row >> 11;
    const float qn = g_qnorm[row], qm = g_qmax[row];
    const float* dp = g_qdash + (size_t)row * MP_;
    const float* ks = g_ksum + b * MP_;
    float s = 0.f;
#pragma unroll
    for (int i = 0; i < 9; i++) {
        int m = lane + 32 * i;
        if (m < M_) {
            float qp = RATIO_ * (__expf(dp[m] - qn - qm) + EPS_);
            s += qp * ks[m];
        }
    }
#pragma unroll
    for (int o = 16; o; o >>= 1) s += __shfl_xor_sync(0xffffffffu, s, o);
    if (lane == 0) g_dinv[row] = 1.f / s;
}

// ---------------- K3: out = (qp @ ctx) * dinv (exp fused into staging) -----------
// Grid (16 row-tiles of 128, 64 b). 256 thr (16 ty x 16 tx), 8x4 micro, K=288 m.
__global__ __launch_bounds__(256, 3)
void k3_out(float* __restrict__ out) {
    __shared__ float qp_s[16][132];
    __shared__ float ctx_s[16][68];
    const int tid = threadIdx.x;
    const int b   = blockIdx.y;
    const int r0  = blockIdx.x * 128;
    const int ty = tid >> 4, tx = tid & 15;
    const int rl = tid & 127, mh = tid >> 7;   // staging mapping
    const int gr_l = b * N_ + r0 + rl;
    const float qn = g_qnorm[gr_l], qm = g_qmax[gr_l];

    float acc[8][4];
#pragma unroll
    for (int i = 0; i < 8; i++)
#pragma unroll
        for (int j = 0; j < 4; j++) acc[i][j] = 0.f;

    for (int ck = 0; ck < 18; ck++) {
        const int m0 = ck * 16;
        {
            const float* src = g_qdash + (size_t)gr_l * MP_ + m0 + mh * 8;
            float4 d0 = *(const float4*)src;
            float4 d1 = *(const float4*)(src + 4);
            float dv[8] = {d0.x, d0.y, d0.z, d0.w, d1.x, d1.y, d1.z, d1.w};
#pragma unroll
            for (int j = 0; j < 8; j++) {
                int mg = m0 + mh * 8 + j;
                qp_s[mh * 8 + j][rl] =
                    (mg < M_) ? RATIO_ * (__expf(dv[j] - qn - qm) + EPS_) : 0.f;
            }
        }
        for (int i = tid; i < 1024; i += 256) {
            int mm = i >> 6, e = i & 63;
            ctx_s[mm][e] = g_ctx[(b * MP_ + m0 + mm) * 64 + e];
        }
        __syncthreads();
#pragma unroll
        for (int mm = 0; mm < 16; mm++) {
            float4 a0 = *(const float4*)&qp_s[mm][ty * 8];
            float4 a1 = *(const float4*)&qp_s[mm][ty * 8 + 4];
            float4 b4 = *(const float4*)&ctx_s[mm][tx * 4];
            float av[8] = {a0.x, a0.y, a0.z, a0.w, a1.x, a1.y, a1.z, a1.w};
            float bv[4] = {b4.x, b4.y, b4.z, b4.w};
#pragma unroll
            for (int i = 0; i < 8; i++)
#pragma unroll
                for (int j = 0; j < 4; j++) acc[i][j] += av[i] * bv[j];
        }
        __syncthreads();
    }
#pragma unroll
    for (int i = 0; i < 8; i++) {
        int gr = b * N_ + r0 + ty * 8 + i;
        float di = g_dinv[gr];
        *(float4*)&out[(size_t)gr * 64 + tx * 4] =
            make_float4(acc[i][0] * di, acc[i][1] * di, acc[i][2] * di, acc[i][3] * di);
    }
}

// ---------------- launcher -------------------------------------------------------
extern "C" void kernel_launch(void* const* d_in, const int* in_sizes, int n_in,
                              void* d_out, int out_size) {
    const float* q    = (const float*)d_in[0];
    const float* k    = (const float*)d_in[1];
    const float* v    = (const float*)d_in[2];
    const float* proj = (const float*)d_in[3];
    float* out = (float*)d_out;

    k0_zero<<<4608, 256>>>();
    k1_proj<<<dim3(1024, 2), 288>>>(q, proj, 1);
    k1_proj<<<dim3(1024, 2), 288>>>(k, proj, 0);
    k1b_max<<<32768, 256>>>();
    k1c_kmax<<<1, 256>>>();
    k2_ctx<<<dim3(3, 4, 64), 192>>>(v);
    k2b_ksum<<<72, 256>>>();
    k3b_dinv<<<16384, 256>>>();
    k3_out<<<dim3(16, 64), 256>>>(out);
}

// round 3
// speedup vs baseline: 1.9193x; 1.9193x over previous
#include <cuda_runtime.h>
#include <cuda_bf16.h>
#include <cstdint>

// Performer (FAVOR+) attention via mma.sync bf16 (split hi/lo, 3-MMA) GEMMs.
// B=64, N=2048, d=64, m=266 (padded to 288).

#define B_      64
#define N_      2048
#define D_      64
#define M_      266
#define MP_     288
#define NROWS_  (B_ * N_)
#define SCALE_  0.35355339059327373f   // 64^-0.25
#define NORMC_  0.0625f                // 0.5 * 64^-0.5
#define RATIO_  0.06131393394849658f   // 266^-0.5
#define EPS_    1e-4f

// ---------------- scratch ----------------
__device__ float    g_qdash[NROWS_ * MP_];
__device__ float    g_kdash[NROWS_ * MP_];
__device__ float    g_qnorm[NROWS_];
__device__ float    g_knorm[NROWS_];
__device__ uint32_t g_qmaxU[NROWS_];
__device__ float    g_kpart[2048];
__device__ float    g_kmaxf;
__device__ float    g_ctxT[B_ * D_ * MP_];   // [b][e][m]
__device__ float    g_ksum[B_ * MP_];

// ---------------- helpers ----------------
__device__ __forceinline__ void mma_bf16(float* d, const uint32_t* a,
                                         uint32_t b0, uint32_t b1) {
    asm volatile(
        "mma.sync.aligned.m16n8k16.row.col.f32.bf16.bf16.f32 "
        "{%0,%1,%2,%3}, {%4,%5,%6,%7}, {%8,%9}, {%0,%1,%2,%3};\n"
        : "+f"(d[0]), "+f"(d[1]), "+f"(d[2]), "+f"(d[3])
        : "r"(a[0]), "r"(a[1]), "r"(a[2]), "r"(a[3]), "r"(b0), "r"(b1));
}
// split fp32 pair (x=k, y=k+1) -> hi bf16x2 (low half = x), lo bf16x2
__device__ __forceinline__ void split_pack(float x, float y, uint32_t& hi, uint32_t& lo) {
    __nv_bfloat16 hx = __float2bfloat16(x);
    __nv_bfloat16 hy = __float2bfloat16(y);
    __nv_bfloat16 lx = __float2bfloat16(x - __bfloat162float(hx));
    __nv_bfloat16 ly = __float2bfloat16(y - __bfloat162float(hy));
    hi = (uint32_t)__bfloat16_as_ushort(hx) | ((uint32_t)__bfloat16_as_ushort(hy) << 16);
    lo = (uint32_t)__bfloat16_as_ushort(lx) | ((uint32_t)__bfloat16_as_ushort(ly) << 16);
}
// order-preserving float<->uint for atomicMax
__device__ __forceinline__ uint32_t fenc(float x) {
    uint32_t u = __float_as_uint(x);
    return (u & 0x80000000u) ? ~u : (u | 0x80000000u);
}
__device__ __forceinline__ float fdec(uint32_t u) {
    return (u & 0x80000000u) ? __uint_as_float(u & 0x7FFFFFFFu) : __uint_as_float(~u);
}

// ---------------- K0: zero accumulators (graph replays!) ----------------
__global__ void k0_zero() {
    int i = blockIdx.x * 256 + threadIdx.x;
    if (i < B_ * D_ * MP_) g_ctxT[i] = 0.f;
    if (i < B_ * MP_) g_ksum[i] = 0.f;
    if (i < NROWS_) g_qmaxU[i] = 0u;     // 0 < every fenc(real)
}

// ---------------- norms ----------------
__global__ void knorms(const float* __restrict__ q, const float* __restrict__ k) {
    const int warp = threadIdx.x >> 5, lane = threadIdx.x & 31;
    const bool isq = blockIdx.x < 16384;
    const int row = (isq ? blockIdx.x : blockIdx.x - 16384) * 8 + warp;
    const float2 v = ((const float2*)((isq ? q : k) + (size_t)row * 64))[lane];
    float s = v.x * v.x + v.y * v.y;
#pragma unroll
    for (int o = 16; o; o >>= 1) s += __shfl_xor_sync(0xffffffffu, s, o);
    if (!lane) (isq ? g_qnorm : g_knorm)[row] = NORMC_ * s;
}

// ---------------- K1: dash = SCALE * X @ P^T (split-bf16 mma) ------------------
// CTA: 128 rows x 144 feats. grid (1024 rowblocks, 2 fblocks). 256 thr, 8 warps
// (4 row x 2 feat), warp tile 32x72 (2 m16 x 9 n8). K=64 = 4 ksteps x 3 splits.
#define K1_AH 0
#define K1_AL 18432
#define K1_BH 36864
#define K1_BL 57600
#define K1_RM 78336
#define K1_SM 78848

__global__ __launch_bounds__(256)
void k1_proj(const float* __restrict__ X, const float* __restrict__ P, int isq) {
    extern __shared__ char sm[];
    uint32_t* Ah = (uint32_t*)(sm + K1_AH);
    uint32_t* Al = (uint32_t*)(sm + K1_AL);
    uint32_t* Bh = (uint32_t*)(sm + K1_BH);
    uint32_t* Bl = (uint32_t*)(sm + K1_BL);
    uint32_t* rmaxU = (uint32_t*)(sm + K1_RM);

    const int tid = threadIdx.x, w = tid >> 5, l = tid & 31;
    const int g = l >> 2, t = l & 3;
    const int row0 = blockIdx.x * 128;
    const int m0 = blockIdx.y * 144;
    const int r_off = (w & 3) * 32;
    const int f_off = (w >> 2) * 72;
    float* dash = isq ? g_qdash : g_kdash;

    // stage A = X tile: 128 rows x 32 k-pairs, row stride 36 u32
    const float4* X4 = (const float4*)X;
    for (int i = tid; i < 2048; i += 256) {
        const int r = i >> 4, c4 = i & 15;
        float4 v = X4[(size_t)(row0 + r) * 16 + c4];
        uint32_t h0, l0, h1, l1;
        split_pack(v.x, v.y, h0, l0);
        split_pack(v.z, v.w, h1, l1);
        Ah[r * 36 + 2 * c4] = h0; Ah[r * 36 + 2 * c4 + 1] = h1;
        Al[r * 36 + 2 * c4] = l0; Al[r * 36 + 2 * c4 + 1] = l1;
    }
    // stage B = SCALE * P tile: 144 feats x 32 k-pairs
    const float4* P4 = (const float4*)P;
    for (int i = tid; i < 2304; i += 256) {
        const int m = i >> 4, c4 = i & 15;
        float4 v = make_float4(0.f, 0.f, 0.f, 0.f);
        if (m0 + m < M_) v = P4[(size_t)(m0 + m) * 16 + c4];
        uint32_t h0, l0, h1, l1;
        split_pack(v.x * SCALE_, v.y * SCALE_, h0, l0);
        split_pack(v.z * SCALE_, v.w * SCALE_, h1, l1);
        Bh[m * 36 + 2 * c4] = h0; Bh[m * 36 + 2 * c4 + 1] = h1;
        Bl[m * 36 + 2 * c4] = l0; Bl[m * 36 + 2 * c4 + 1] = l1;
    }
    if (tid < 128) rmaxU[tid] = 0u;
    __syncthreads();

    float acc[2][9][4];
#pragma unroll
    for (int mi = 0; mi < 2; mi++)
#pragma unroll
        for (int ni = 0; ni < 9; ni++)
#pragma unroll
            for (int j = 0; j < 4; j++) acc[mi][ni][j] = 0.f;

#pragma unroll
    for (int kk = 0; kk < 4; kk++) {
        const int c = 8 * kk + t;
        uint32_t ah[2][4], al[2][4];
#pragma unroll
        for (int mi = 0; mi < 2; mi++) {
            const int rA = r_off + 16 * mi;
            ah[mi][0] = Ah[(rA + g) * 36 + c];
            ah[mi][1] = Ah[(rA + 8 + g) * 36 + c];
            ah[mi][2] = Ah[(rA + g) * 36 + c + 4];
            ah[mi][3] = Ah[(rA + 8 + g) * 36 + c + 4];
            al[mi][0] = Al[(rA + g) * 36 + c];
            al[mi][1] = Al[(rA + 8 + g) * 36 + c];
            al[mi][2] = Al[(rA + g) * 36 + c + 4];
            al[mi][3] = Al[(rA + 8 + g) * 36 + c + 4];
        }
#pragma unroll
        for (int ni = 0; ni < 9; ni++) {
            const int cw = (f_off + 8 * ni + g) * 36;
            uint32_t bh0 = Bh[cw + c], bh1 = Bh[cw + c + 4];
            uint32_t bl0 = Bl[cw + c], bl1 = Bl[cw + c + 4];
#pragma unroll
            for (int mi = 0; mi < 2; mi++) {
                mma_bf16(acc[mi][ni], ah[mi], bh0, bh1);
                mma_bf16(acc[mi][ni], ah[mi], bl0, bl1);
                mma_bf16(acc[mi][ni], al[mi], bh0, bh1);
            }
        }
    }

    // row maxes (masked to m<266) -> smem atomicMax
    float rmx[2][2] = {{-3.4e38f, -3.4e38f}, {-3.4e38f, -3.4e38f}};
#pragma unroll
    for (int mi = 0; mi < 2; mi++)
#pragma unroll
        for (int ni = 0; ni < 9; ni++) {
            const int cb = m0 + f_off + 8 * ni + 2 * t;
            if (cb < M_) {
                rmx[mi][0] = fmaxf(rmx[mi][0], acc[mi][ni][0]);
                rmx[mi][1] = fmaxf(rmx[mi][1], acc[mi][ni][2]);
            }
            if (cb + 1 < M_) {
                rmx[mi][0] = fmaxf(rmx[mi][0], acc[mi][ni][1]);
                rmx[mi][1] = fmaxf(rmx[mi][1], acc[mi][ni][3]);
            }
        }
#pragma unroll
    for (int mi = 0; mi < 2; mi++) {
        atomicMax(&rmaxU[r_off + 16 * mi + g], fenc(rmx[mi][0]));
        atomicMax(&rmaxU[r_off + 16 * mi + 8 + g], fenc(rmx[mi][1]));
    }

    // store dash
#pragma unroll
    for (int mi = 0; mi < 2; mi++) {
        const int rg = row0 + r_off + 16 * mi + g;
#pragma unroll
        for (int ni = 0; ni < 9; ni++) {
            const int col = m0 + f_off + 8 * ni + 2 * t;
            *(float2*)&dash[(size_t)rg * MP_ + col] =
                make_float2(acc[mi][ni][0], acc[mi][ni][1]);
            *(float2*)&dash[(size_t)(rg + 8) * MP_ + col] =
                make_float2(acc[mi][ni][2], acc[mi][ni][3]);
        }
    }
    __syncthreads();

    if (isq) {
        if (tid < 128) atomicMax(&g_qmaxU[row0 + tid], rmaxU[tid]);
    } else {
        if (tid < 32) {
            uint32_t u = max(max(rmaxU[tid], rmaxU[tid + 32]),
                             max(rmaxU[tid + 64], rmaxU[tid + 96]));
#pragma unroll
            for (int o = 16; o; o >>= 1)
                u = max(u, __shfl_xor_sync(0xffffffffu, u, o));
            if (tid == 0) g_kpart[blockIdx.y * 1024 + blockIdx.x] = fdec(u);
        }
    }
}

// ---------------- K1c: global k max ----------------
__global__ void k1c_kmax() {
    __shared__ float sm[256];
    float mx = -3.4e38f;
    for (int i = threadIdx.x; i < 2048; i += 256) mx = fmaxf(mx, g_kpart[i]);
    sm[threadIdx.x] = mx;
    __syncthreads();
    for (int s = 128; s; s >>= 1) {
        if (threadIdx.x < s) sm[threadIdx.x] = fmaxf(sm[threadIdx.x], sm[threadIdx.x + s]);
        __syncthreads();
    }
    if (threadIdx.x == 0) g_kmaxf = sm[0];
}

// ---------------- K2: ctxT[e][m] += sum_n v[n,e]*kp[n,m]  ----------------------
// A = v^T (M=64 e), B = kp (N=96 feats/CTA), K = 512 n per CTA (4 n-splits).
// 192 thr, 6 warps (2e x 3m), warp tile 32x32 (2 m16 x 4 n8). exp+ksum fused.
__global__ __launch_bounds__(192)
void k2_ctx(const float* __restrict__ v) {
    __shared__ uint32_t VAh[64 * 12], VAl[64 * 12];
    __shared__ uint32_t KBh[96 * 12], KBl[96 * 12];

    const int tid = threadIdx.x, w = tid >> 5, l = tid & 31;
    const int g = l >> 2, t = l & 3;
    const int b = blockIdx.z;
    const int m0 = blockIdx.x * 96;
    const int nbase = blockIdx.y * 512;
    const int bN = b * N_;
    const float kmax = g_kmaxf;

    const int mloc = l + 32 * (w % 3);     // staging m (0..95)
    const int sgrp = w / 3;                // 0/1 -> pair groups
    const int mglob = m0 + mloc;
    const bool mval = mglob < M_;

    const int e_off = (w & 1) * 32;
    const int m_off = (w >> 1) * 32;

    float acc[2][4][4];
#pragma unroll
    for (int mi = 0; mi < 2; mi++)
#pragma unroll
        for (int ni = 0; ni < 4; ni++)
#pragma unroll
            for (int j = 0; j < 4; j++) acc[mi][ni][j] = 0.f;
    float kslocal = 0.f;

    for (int ck = 0; ck < 32; ck++) {
        const int n0 = nbase + ck * 16;
        // stage kp (B): all warps
#pragma unroll
        for (int ii = 0; ii < 4; ii++) {
            const int i = 4 * sgrp + ii;
            const int n = n0 + 2 * i;
            float d0 = g_kdash[(size_t)(bN + n) * MP_ + mglob];
            float d1 = g_kdash[(size_t)(bN + n + 1) * MP_ + mglob];
            float nm0 = g_knorm[bN + n], nm1 = g_knorm[bN + n + 1];
            float kp0 = mval ? RATIO_ * (__expf(d0 - nm0 - kmax) + EPS_) : 0.f;
            float kp1 = mval ? RATIO_ * (__expf(d1 - nm1 - kmax) + EPS_) : 0.f;
            kslocal += kp0 + kp1;
            uint32_t h, lo;
            split_pack(kp0, kp1, h, lo);
            KBh[mloc * 12 + i] = h; KBl[mloc * 12 + i] = lo;
        }
        // stage v (A): warps 0-3
        if (w < 4) {
            const int e = l + 32 * (w & 1);
            const int vg = w >> 1;
#pragma unroll
            for (int ii = 0; ii < 4; ii++) {
                const int i = 4 * vg + ii;
                const int n = n0 + 2 * i;
                float v0 = v[(size_t)(bN + n) * 64 + e];
                float v1 = v[(size_t)(bN + n + 1) * 64 + e];
                uint32_t h, lo;
                split_pack(v0, v1, h, lo);
                VAh[e * 12 + i] = h; VAl[e * 12 + i] = lo;
            }
        }
        __syncthreads();
        // mma
        uint32_t ah[2][4], al[2][4];
#pragma unroll
        for (int mi = 0; mi < 2; mi++) {
            const int eR = e_off + 16 * mi;
            ah[mi][0] = VAh[(eR + g) * 12 + t];
            ah[mi][1] = VAh[(eR + 8 + g) * 12 + t];
            ah[mi][2] = VAh[(eR + g) * 12 + t + 4];
            ah[mi][3] = VAh[(eR + 8 + g) * 12 + t + 4];
            al[mi][0] = VAl[(eR + g) * 12 + t];
            al[mi][1] = VAl[(eR + 8 + g) * 12 + t];
            al[mi][2] = VAl[(eR + g) * 12 + t + 4];
            al[mi][3] = VAl[(eR + 8 + g) * 12 + t + 4];
        }
#pragma unroll
        for (int ni = 0; ni < 4; ni++) {
            const int cw = (m_off + 8 * ni + g) * 12;
            uint32_t bh0 = KBh[cw + t], bh1 = KBh[cw + t + 4];
            uint32_t bl0 = KBl[cw + t], bl1 = KBl[cw + t + 4];
#pragma unroll
            for (int mi = 0; mi < 2; mi++) {
                mma_bf16(acc[mi][ni], ah[mi], bh0, bh1);
                mma_bf16(acc[mi][ni], ah[mi], bl0, bl1);
                mma_bf16(acc[mi][ni], al[mi], bh0, bh1);
            }
        }
        __syncthreads();
    }

    if (mval && kslocal != 0.f) atomicAdd(&g_ksum[b * MP_ + mglob], kslocal);

#pragma unroll
    for (int mi = 0; mi < 2; mi++) {
        const int e0 = e_off + 16 * mi + g;
#pragma unroll
        for (int ni = 0; ni < 4; ni++) {
            const int mc = m0 + m_off + 8 * ni + 2 * t;
            float* p0 = &g_ctxT[((size_t)(b * 64 + e0)) * MP_ + mc];
            float* p1 = &g_ctxT[((size_t)(b * 64 + e0 + 8)) * MP_ + mc];
            atomicAdd(p0, acc[mi][ni][0]);
            atomicAdd(p0 + 1, acc[mi][ni][1]);
            atomicAdd(p1, acc[mi][ni][2]);
            atomicAdd(p1 + 1, acc[mi][ni][3]);
        }
    }
}

// ---------------- K3: out = (qp @ ctxT^T) * dinv (dinv fused) ------------------
// CTA: 128 rows x 64 e, K=288 (9 chunks of 32). 256 thr, 8 warps (4r x 2e),
// warp tile 32x32. qp exp + D=qp.ksum partial fused into staging.
__global__ __launch_bounds__(256)
void k3_out(float* __restrict__ out) {
    __shared__ uint32_t QAh[128 * 20], QAl[128 * 20];
    __shared__ uint32_t CBh[64 * 20], CBl[64 * 20];
    __shared__ float dinv_s[128];

    const int tid = threadIdx.x, w = tid >> 5, l = tid & 31;
    const int g = l >> 2, t = l & 3;
    const int b = blockIdx.y;
    const int r0 = blockIdx.x * 128;
    const int bN = b * N_;

    // staging mappings
    const int sr = tid >> 1;              // row 0..127
    const int shalf = tid & 1;            // which 16-m half of chunk
    const int se = tid >> 2;              // e 0..63
    const int sq4 = tid & 3;

    const int gr = bN + r0 + sr;
    const float qn = g_qnorm[gr];
    const float qm = fdec(g_qmaxU[gr]);

    const int r_off = (w & 3) * 32;
    const int e_off = (w >> 2) * 32;

    float acc[2][4][4];
#pragma unroll
    for (int mi = 0; mi < 2; mi++)
#pragma unroll
        for (int ni = 0; ni < 4; ni++)
#pragma unroll
            for (int j = 0; j < 4; j++) acc[mi][ni][j] = 0.f;
    float Dpart = 0.f;

    for (int ck = 0; ck < 9; ck++) {
        const int m0 = 32 * ck;
        // stage qp (A): 16 floats per thread, fused D partial
        {
            const float* src = g_qdash + (size_t)gr * MP_ + m0 + 16 * shalf;
            const float* kss = g_ksum + b * MP_ + m0 + 16 * shalf;
#pragma unroll
            for (int j = 0; j < 4; j++) {
                float4 d = *(const float4*)(src + 4 * j);
                float4 ks = *(const float4*)(kss + 4 * j);
                const int mbase = m0 + 16 * shalf + 4 * j;
                float q0 = (mbase < M_) ? RATIO_ * (__expf(d.x - qn - qm) + EPS_) : 0.f;
                float q1 = (mbase + 1 < M_) ? RATIO_ * (__expf(d.y - qn - qm) + EPS_) : 0.f;
                float q2 = (mbase + 2 < M_) ? RATIO_ * (__expf(d.z - qn - qm) + EPS_) : 0.f;
                float q3 = (mbase + 3 < M_) ? RATIO_ * (__expf(d.w - qn - qm) + EPS_) : 0.f;
                Dpart += q0 * ks.x + q1 * ks.y + q2 * ks.z + q3 * ks.w;
                uint32_t h0, l0, h1, l1;
                split_pack(q0, q1, h0, l0);
                split_pack(q2, q3, h1, l1);
                const int i = 8 * shalf + 2 * j;
                QAh[sr * 20 + i] = h0; QAh[sr * 20 + i + 1] = h1;
                QAl[sr * 20 + i] = l0; QAl[sr * 20 + i + 1] = l1;
            }
        }
        // stage ctxT (B): 8 floats per thread
        {
            const float* src = g_ctxT + ((size_t)(b * 64 + se)) * MP_ + m0 + 8 * sq4;
#pragma unroll
            for (int j = 0; j < 2; j++) {
                float4 c = *(const float4*)(src + 4 * j);
                uint32_t h0, l0, h1, l1;
                split_pack(c.x, c.y, h0, l0);
                split_pack(c.z, c.w, h1, l1);
                const int i = 4 * sq4 + 2 * j;
                CBh[se * 20 + i] = h0; CBh[se * 20 + i + 1] = h1;
                CBl[se * 20 + i] = l0; CBl[se * 20 + i + 1] = l1;
            }
        }
        __syncthreads();
#pragma unroll
        for (int kk = 0; kk < 2; kk++) {
            const int c = 8 * kk + t;
            uint32_t ah[2][4], al[2][4];
#pragma unroll
            for (int mi = 0; mi < 2; mi++) {
                const int rA = r_off + 16 * mi;
                ah[mi][0] = QAh[(rA + g) * 20 + c];
                ah[mi][1] = QAh[(rA + 8 + g) * 20 + c];
                ah[mi][2] = QAh[(rA + g) * 20 + c + 4];
                ah[mi][3] = QAh[(rA + 8 + g) * 20 + c + 4];
                al[mi][0] = QAl[(rA + g) * 20 + c];
                al[mi][1] = QAl[(rA + 8 + g) * 20 + c];
                al[mi][2] = QAl[(rA + g) * 20 + c + 4];
                al[mi][3] = QAl[(rA + 8 + g) * 20 + c + 4];
            }
#pragma unroll
            for (int ni = 0; ni < 4; ni++) {
                const int cw = (e_off + 8 * ni + g) * 20;
                uint32_t bh0 = CBh[cw + c], bh1 = CBh[cw + c + 4];
                uint32_t bl0 = CBl[cw + c], bl1 = CBl[cw + c + 4];
#pragma unroll
                for (int mi = 0; mi < 2; mi++) {
                    mma_bf16(acc[mi][ni], ah[mi], bh0, bh1);
                    mma_bf16(acc[mi][ni], ah[mi], bl0, bl1);
                    mma_bf16(acc[mi][ni], al[mi], bh0, bh1);
                }
            }
        }
        __syncthreads();
    }

    // finish D^-1: rows staged by thread pairs (t, t^1)
    Dpart += __shfl_xor_sync(0xffffffffu, Dpart, 1);
    if ((tid & 1) == 0) dinv_s[sr] = 1.f / Dpart;
    __syncthreads();

#pragma unroll
    for (int mi = 0; mi < 2; mi++) {
        const int rl0 = r_off + 16 * mi + g;
        const float di0 = dinv_s[rl0];
        const float di1 = dinv_s[rl0 + 8];
#pragma unroll
        for (int ni = 0; ni < 4; ni++) {
            const int col = e_off + 8 * ni + 2 * t;
            *(float2*)&out[((size_t)(bN + r0 + rl0)) * 64 + col] =
                make_float2(acc[mi][ni][0] * di0, acc[mi][ni][1] * di0);
            *(float2*)&out[((size_t)(bN + r0 + rl0 + 8)) * 64 + col] =
                make_float2(acc[mi][ni][2] * di1, acc[mi][ni][3] * di1);
        }
    }
}

// ---------------- launcher ----------------
extern "C" void kernel_launch(void* const* d_in, const int* in_sizes, int n_in,
                              void* d_out, int out_size) {
    const float* q    = (const float*)d_in[0];
    const float* k    = (const float*)d_in[1];
    const float* v    = (const float*)d_in[2];
    const float* proj = (const float*)d_in[3];
    float* out = (float*)d_out;

    static int configured = 0;
    if (!configured) {
        cudaFuncSetAttribute(k1_proj, cudaFuncAttributeMaxDynamicSharedMemorySize, K1_SM);
        configured = 1;
    }

    k0_zero<<<4608, 256>>>();
    knorms<<<32768, 256>>>(q, k);
    k1_proj<<<dim3(1024, 2), 256, K1_SM>>>(q, proj, 1);
    k1_proj<<<dim3(1024, 2), 256, K1_SM>>>(k, proj, 0);
    k1c_kmax<<<1, 256>>>();
    k2_ctx<<<dim3(3, 4, 64), 192>>>(v);
    k3_out<<<dim3(16, 64), 256>>>(out);
}